// round 10
// baseline (speedup 1.0000x reference)
#include <cuda_runtime.h>
#include <cuda_bf16.h>

// LoRA: out[b,s,o] = scaling * sum_r ( sum_i x[b,s,i] * A[r,i] ) * B[o,r]
// x: [4, 8192, 1024] f32   A: [4, 1024] f32   B: [1024, 4] f32   scaling = 0.25
//
// R4 reg-cap-32 -> MLP 1 (232us). R5 no cap -> occ 11% (69us). R6 cap 84 ->
// L1tex 82.6% (49.9us). R7 2-row LDS amortization -> DRAM 66% (47.5us).
// R8 packed f32x2: issue 28->20% but dur flat -> latency-bound, not issue-bound.
// R9: 2-stage software pipeline. Each warp owns exactly 2 pairs; pair B's
// 16 LDG.128 are issued right after pass1 consumes pair A's registers (WAR
// reuse, no extra regs), so B's DRAM latency hides under A's butterfly +
// pass2 + stores. Only the prologue load is exposed.

#define LORA_NROWS   (4 * 8192)   // 32768 token rows
#define LORA_NF4     256          // 1024 floats / 4 -> 16B chunks per row
#define LORA_BLOCK   256
#define LORA_WARPS   8
#define LORA_GRID    1024
#define LORA_NWARPS  (LORA_GRID * LORA_WARPS)      // 8192 warps
#define LORA_PAIRS   (LORA_NROWS / 2)              // 16384 row-pairs = 2 per warp
#define LORA_SCALE   0.25f

// ---- packed fp32x2 helpers (SASS: FFMA2 / FMUL2; ptxas won't emit from C++) ----
__device__ __forceinline__ unsigned long long f2fma(unsigned long long a,
                                                    unsigned long long b,
                                                    unsigned long long c) {
    unsigned long long d;
    asm("fma.rn.f32x2 %0, %1, %2, %3;" : "=l"(d) : "l"(a), "l"(b), "l"(c));
    return d;
}
__device__ __forceinline__ unsigned long long f2mul(unsigned long long a,
                                                    unsigned long long b) {
    unsigned long long d;
    asm("mul.rn.f32x2 %0, %1, %2;" : "=l"(d) : "l"(a), "l"(b));
    return d;
}
__device__ __forceinline__ unsigned long long pk2(float lo, float hi) {
    unsigned long long r;
    asm("mov.b64 %0, {%1, %2};" : "=l"(r) : "f"(lo), "f"(hi));
    return r;
}
__device__ __forceinline__ float2 unpk2(unsigned long long v) {
    float2 f;
    asm("mov.b64 {%0, %1}, %2;" : "=f"(f.x), "=f"(f.y) : "l"(v));
    return f;
}
__device__ __forceinline__ ulonglong2 ldcs16(const ulonglong2* p) {
    ulonglong2 v;
    asm("ld.global.cs.v2.u64 {%0, %1}, [%2];" : "=l"(v.x), "=l"(v.y) : "l"(p));
    return v;
}
__device__ __forceinline__ void stcs16(ulonglong2* p, ulonglong2 v) {
    asm("st.global.cs.v2.u64 [%0], {%1, %2};" :: "l"(p), "l"(v.x), "l"(v.y) : "memory");
}

struct PairSums { float p0, p1, p2, p3, q0, q1, q2, q3; };

// Pass 1 on registers xv (consumes them) -> folded, reduced, scaled sums.
__device__ __forceinline__ PairSums pass1_reduce(const ulonglong2* __restrict__ sA2,
                                                 const ulonglong2 xv0[8],
                                                 const ulonglong2 xv1[8],
                                                 int lane)
{
    unsigned long long a00 = 0, a01 = 0, a02 = 0, a03 = 0;
    unsigned long long a10 = 0, a11 = 0, a12 = 0, a13 = 0;
    #pragma unroll
    for (int j = 0; j < 8; j++) {
        int idx = j * 32 + lane;
        ulonglong2 t0 = sA2[0 * 256 + idx];
        ulonglong2 t1 = sA2[1 * 256 + idx];
        ulonglong2 t2 = sA2[2 * 256 + idx];
        ulonglong2 t3 = sA2[3 * 256 + idx];
        a00 = f2fma(xv0[j].x, t0.x, a00); a00 = f2fma(xv0[j].y, t0.y, a00);
        a01 = f2fma(xv0[j].x, t1.x, a01); a01 = f2fma(xv0[j].y, t1.y, a01);
        a02 = f2fma(xv0[j].x, t2.x, a02); a02 = f2fma(xv0[j].y, t2.y, a02);
        a03 = f2fma(xv0[j].x, t3.x, a03); a03 = f2fma(xv0[j].y, t3.y, a03);
        a10 = f2fma(xv1[j].x, t0.x, a10); a10 = f2fma(xv1[j].y, t0.y, a10);
        a11 = f2fma(xv1[j].x, t1.x, a11); a11 = f2fma(xv1[j].y, t1.y, a11);
        a12 = f2fma(xv1[j].x, t2.x, a12); a12 = f2fma(xv1[j].y, t2.y, a12);
        a13 = f2fma(xv1[j].x, t3.x, a13); a13 = f2fma(xv1[j].y, t3.y, a13);
    }
    PairSums s;
    float2 f;
    f = unpk2(a00); s.p0 = f.x + f.y;
    f = unpk2(a01); s.p1 = f.x + f.y;
    f = unpk2(a02); s.p2 = f.x + f.y;
    f = unpk2(a03); s.p3 = f.x + f.y;
    f = unpk2(a10); s.q0 = f.x + f.y;
    f = unpk2(a11); s.q1 = f.x + f.y;
    f = unpk2(a12); s.q2 = f.x + f.y;
    f = unpk2(a13); s.q3 = f.x + f.y;
    return s;
}

__device__ __forceinline__ void reduce_scale(PairSums& s)
{
    #pragma unroll
    for (int off = 16; off > 0; off >>= 1) {
        s.p0 += __shfl_xor_sync(0xffffffffu, s.p0, off);
        s.p1 += __shfl_xor_sync(0xffffffffu, s.p1, off);
        s.p2 += __shfl_xor_sync(0xffffffffu, s.p2, off);
        s.p3 += __shfl_xor_sync(0xffffffffu, s.p3, off);
        s.q0 += __shfl_xor_sync(0xffffffffu, s.q0, off);
        s.q1 += __shfl_xor_sync(0xffffffffu, s.q1, off);
        s.q2 += __shfl_xor_sync(0xffffffffu, s.q2, off);
        s.q3 += __shfl_xor_sync(0xffffffffu, s.q3, off);
    }
    s.p0 *= LORA_SCALE; s.p1 *= LORA_SCALE; s.p2 *= LORA_SCALE; s.p3 *= LORA_SCALE;
    s.q0 *= LORA_SCALE; s.q1 *= LORA_SCALE; s.q2 *= LORA_SCALE; s.q3 *= LORA_SCALE;
}

__device__ __forceinline__ void pass2_store(const ulonglong2* __restrict__ sB0,
                                            const ulonglong2* __restrict__ sB1,
                                            const ulonglong2* __restrict__ sB2,
                                            const ulonglong2* __restrict__ sB3,
                                            const PairSums& s,
                                            ulonglong2* orow0, int lane)
{
    const unsigned long long P0 = pk2(s.p0, s.p0), P1 = pk2(s.p1, s.p1),
                             P2 = pk2(s.p2, s.p2), P3 = pk2(s.p3, s.p3);
    const unsigned long long Q0 = pk2(s.q0, s.q0), Q1 = pk2(s.q1, s.q1),
                             Q2 = pk2(s.q2, s.q2), Q3 = pk2(s.q3, s.q3);
    ulonglong2* orow1 = orow0 + LORA_NF4;
    #pragma unroll
    for (int j = 0; j < 8; j++) {
        int idx = j * 32 + lane;
        ulonglong2 b0 = sB0[idx];
        ulonglong2 b1 = sB1[idx];
        ulonglong2 b2 = sB2[idx];
        ulonglong2 b3 = sB3[idx];
        ulonglong2 o0, o1;
        o0.x = f2fma(P0, b0.x, f2fma(P1, b1.x, f2fma(P2, b2.x, f2mul(P3, b3.x))));
        o0.y = f2fma(P0, b0.y, f2fma(P1, b1.y, f2fma(P2, b2.y, f2mul(P3, b3.y))));
        o1.x = f2fma(Q0, b0.x, f2fma(Q1, b1.x, f2fma(Q2, b2.x, f2mul(Q3, b3.x))));
        o1.y = f2fma(Q0, b0.y, f2fma(Q1, b1.y, f2fma(Q2, b2.y, f2mul(Q3, b3.y))));
        stcs16(&orow0[idx], o0);
        stcs16(&orow1[idx], o1);
    }
}

__global__ __launch_bounds__(LORA_BLOCK, 2)
void lora_fused_kernel(const float* __restrict__ x,
                       const float* __restrict__ A,
                       const float* __restrict__ B,
                       float* __restrict__ out)
{
    __shared__ float sA[4 * 1024];   // rank-major, same as global A layout
    __shared__ float sBt[4 * 1024];  // TRANSPOSED: sBt[r*1024 + o] = B[o*4 + r]

    const int tid = threadIdx.x;

    // ---- Stage A (direct float4 copy) and B (transpose) into smem ----
    {
        const float4* A4  = reinterpret_cast<const float4*>(A);
        float4*       sA4 = reinterpret_cast<float4*>(sA);
        #pragma unroll
        for (int i = 0; i < 4; i++)
            sA4[tid + i * 256] = A4[tid + i * 256];

        const float4* B4 = reinterpret_cast<const float4*>(B);  // one float4 = one B row
        #pragma unroll
        for (int i = 0; i < 4; i++) {
            int o = tid + i * 256;
            float4 b = B4[o];
            sBt[0 * 1024 + o] = b.x;
            sBt[1 * 1024 + o] = b.y;
            sBt[2 * 1024 + o] = b.z;
            sBt[3 * 1024 + o] = b.w;
        }
    }
    __syncthreads();

    const int lane = tid & 31;
    const int wid  = tid >> 5;
    const int warp_global = blockIdx.x * LORA_WARPS + wid;

    const ulonglong2* sA2 = reinterpret_cast<const ulonglong2*>(sA);
    const ulonglong2* sB0 = reinterpret_cast<const ulonglong2*>(sBt);
    const ulonglong2* sB1 = reinterpret_cast<const ulonglong2*>(sBt + 1024);
    const ulonglong2* sB2 = reinterpret_cast<const ulonglong2*>(sBt + 2048);
    const ulonglong2* sB3 = reinterpret_cast<const ulonglong2*>(sBt + 3072);

    // Each warp owns exactly two pairs: pairA and pairA + NWARPS.
    const size_t rowA = (size_t)warp_global * 2;
    const size_t rowB = (size_t)(warp_global + LORA_NWARPS) * 2;

    const ulonglong2* xrA0 = reinterpret_cast<const ulonglong2*>(x) + rowA * LORA_NF4;
    const ulonglong2* xrB0 = reinterpret_cast<const ulonglong2*>(x) + rowB * LORA_NF4;
    ulonglong2* orA = reinterpret_cast<ulonglong2*>(out) + rowA * LORA_NF4;
    ulonglong2* orB = reinterpret_cast<ulonglong2*>(out) + rowB * LORA_NF4;

    ulonglong2 xv0[8], xv1[8];

    // ---- Stage 1: load pair A (only exposed latency in the kernel) ----
    #pragma unroll
    for (int j = 0; j < 8; j++) xv0[j] = ldcs16(&xrA0[j * 32 + lane]);
    #pragma unroll
    for (int j = 0; j < 8; j++) xv1[j] = ldcs16(&xrA0[LORA_NF4 + j * 32 + lane]);

    // Pass 1 for A consumes xv...
    PairSums sa = pass1_reduce(sA2, xv0, xv1, lane);

    // ---- ...then immediately refill xv with pair B: these 16 LDG.128 fly
    //      during A's butterfly, pass2 and stores (WAR reuse, no extra regs).
    #pragma unroll
    for (int j = 0; j < 8; j++) xv0[j] = ldcs16(&xrB0[j * 32 + lane]);
    #pragma unroll
    for (int j = 0; j < 8; j++) xv1[j] = ldcs16(&xrB0[LORA_NF4 + j * 32 + lane]);

    reduce_scale(sa);
    pass2_store(sB0, sB1, sB2, sB3, sa, orA, lane);

    // ---- Stage 2: pair B (loads already in flight / landed) ----
    PairSums sb = pass1_reduce(sA2, xv0, xv1, lane);
    reduce_scale(sb);
    pass2_store(sB0, sB1, sB2, sB3, sb, orB, lane);
}

extern "C" void kernel_launch(void* const* d_in, const int* in_sizes, int n_in,
                              void* d_out, int out_size)
{
    const float* x = (const float*)d_in[0];   // [4, 8192, 1024]
    const float* A = (const float*)d_in[1];   // [4, 1024]
    const float* B = (const float*)d_in[2];   // [1024, 4]
    float* out     = (float*)d_out;           // [4, 8192, 1024]

    lora_fused_kernel<<<LORA_GRID, LORA_BLOCK>>>(x, A, B, out);
}

// round 11
// speedup vs baseline: 1.3505x; 1.3505x over previous
#include <cuda_runtime.h>
#include <cuda_bf16.h>

// LoRA: out[b,s,o] = scaling * sum_r ( sum_i x[b,s,i] * A[r,i] ) * B[o,r]
// x: [4, 8192, 1024] f32   A: [4, 1024] f32   B: [1024, 4] f32   scaling = 0.25
//
// History: R4 reg-cap-32/MLP1 (232us) -> R5 no cap/occ11% (69us) -> R6 cap84/
// L1tex 83% (49.9us) -> R7 2-row LDS sharing, DRAM 66%, L1 64% (47.5us) ->
// R8 packed f32x2 neutral -> R9 explicit SW pipeline REGRESSED (63.7us,
// register-liveness serialization). R11: revert to R7 structure, extend the
// winning axis: 4-row blocking. A/B smem tiles shared across 4 rows ->
// wide-LSU ops/row 48 -> 32, smem traffic/row halved. Scalar FMA (R8 showed
// packed is perf-neutral; scalar saves 16 regs). One quad per warp, exact.

#define LORA_NROWS   (4 * 8192)   // 32768 token rows
#define LORA_NF4     256          // 1024 floats / 4 -> float4 chunks per row
#define LORA_BLOCK   256
#define LORA_WARPS   8
#define LORA_GRID    1024         // 8192 warps == 8192 quads, exactly 1 each
#define LORA_SCALE   0.25f

__device__ __forceinline__ float4 ldcs4(const float4* p) {
    float4 v;
    asm("ld.global.cs.v4.f32 {%0, %1, %2, %3}, [%4];"
        : "=f"(v.x), "=f"(v.y), "=f"(v.z), "=f"(v.w) : "l"(p));
    return v;
}
__device__ __forceinline__ void stcs4(float4* p, float4 v) {
    asm("st.global.cs.v4.f32 [%0], {%1, %2, %3, %4};"
        :: "l"(p), "f"(v.x), "f"(v.y), "f"(v.z), "f"(v.w) : "memory");
}

__global__ __launch_bounds__(LORA_BLOCK, 2)
void lora_fused_kernel(const float* __restrict__ x,
                       const float* __restrict__ A,
                       const float* __restrict__ B,
                       float* __restrict__ out)
{
    __shared__ float sA[4 * 1024];   // rank-major, same as global A layout
    __shared__ float sBt[4 * 1024];  // TRANSPOSED: sBt[r*1024 + o] = B[o*4 + r]

    const int tid = threadIdx.x;

    // ---- Stage A (direct float4 copy) and B (transpose) into smem ----
    {
        const float4* A4  = reinterpret_cast<const float4*>(A);
        float4*       sA4 = reinterpret_cast<float4*>(sA);
        #pragma unroll
        for (int i = 0; i < 4; i++)
            sA4[tid + i * 256] = A4[tid + i * 256];

        const float4* B4 = reinterpret_cast<const float4*>(B);  // one float4 = one B row
        #pragma unroll
        for (int i = 0; i < 4; i++) {
            int o = tid + i * 256;
            float4 b = B4[o];
            sBt[0 * 1024 + o] = b.x;
            sBt[1 * 1024 + o] = b.y;
            sBt[2 * 1024 + o] = b.z;
            sBt[3 * 1024 + o] = b.w;
        }
    }
    __syncthreads();

    const int lane = tid & 31;
    const int wid  = tid >> 5;
    const int warp_global = blockIdx.x * LORA_WARPS + wid;

    const float4* sA4c = reinterpret_cast<const float4*>(sA);
    const float4* sB0  = reinterpret_cast<const float4*>(sBt);
    const float4* sB1  = reinterpret_cast<const float4*>(sBt + 1024);
    const float4* sB2  = reinterpret_cast<const float4*>(sBt + 2048);
    const float4* sB3  = reinterpret_cast<const float4*>(sBt + 3072);

    // Each warp owns exactly 4 consecutive rows (8192 warps x 4 = 32768).
    const size_t row0 = (size_t)warp_global * 4;
    const float4* xr = reinterpret_cast<const float4*>(x) + row0 * LORA_NF4;

    float acc[4][4];   // [row][rank]
    #pragma unroll
    for (int r = 0; r < 4; r++)
        #pragma unroll
        for (int k = 0; k < 4; k++) acc[r][k] = 0.f;

    // ---- Pass 1 in two halves; each half: 16-LDG.128 burst (MLP=16),
    //      A tile chunk shared by all 4 rows.
    #pragma unroll
    for (int h = 0; h < 2; h++) {
        float4 xv[4][4];   // [row][chunk-within-half]
        #pragma unroll
        for (int r = 0; r < 4; r++)
            #pragma unroll
            for (int j = 0; j < 4; j++)
                xv[r][j] = ldcs4(&xr[r * LORA_NF4 + (h * 4 + j) * 32 + lane]);

        #pragma unroll
        for (int j = 0; j < 4; j++) {
            int idx = (h * 4 + j) * 32 + lane;
            float4 a0 = sA4c[0 * 256 + idx];
            float4 a1 = sA4c[1 * 256 + idx];
            float4 a2 = sA4c[2 * 256 + idx];
            float4 a3 = sA4c[3 * 256 + idx];
            #pragma unroll
            for (int r = 0; r < 4; r++) {
                float4 v = xv[r][j];
                acc[r][0] = fmaf(v.x, a0.x, fmaf(v.y, a0.y, fmaf(v.z, a0.z, fmaf(v.w, a0.w, acc[r][0]))));
                acc[r][1] = fmaf(v.x, a1.x, fmaf(v.y, a1.y, fmaf(v.z, a1.z, fmaf(v.w, a1.w, acc[r][1]))));
                acc[r][2] = fmaf(v.x, a2.x, fmaf(v.y, a2.y, fmaf(v.z, a2.z, fmaf(v.w, a2.w, acc[r][2]))));
                acc[r][3] = fmaf(v.x, a3.x, fmaf(v.y, a3.y, fmaf(v.z, a3.z, fmaf(v.w, a3.w, acc[r][3]))));
            }
        }
    }

    // ---- Warp butterfly reduce all 16 sums; every lane gets full values ----
    #pragma unroll
    for (int off = 16; off > 0; off >>= 1) {
        #pragma unroll
        for (int r = 0; r < 4; r++) {
            acc[r][0] += __shfl_xor_sync(0xffffffffu, acc[r][0], off);
            acc[r][1] += __shfl_xor_sync(0xffffffffu, acc[r][1], off);
            acc[r][2] += __shfl_xor_sync(0xffffffffu, acc[r][2], off);
            acc[r][3] += __shfl_xor_sync(0xffffffffu, acc[r][3], off);
        }
    }
    #pragma unroll
    for (int r = 0; r < 4; r++)
        #pragma unroll
        for (int k = 0; k < 4; k++) acc[r][k] *= LORA_SCALE;

    // ---- Pass 2: B tile chunk shared by all 4 rows ----
    float4* orow = reinterpret_cast<float4*>(out) + row0 * LORA_NF4;
    #pragma unroll
    for (int j = 0; j < 8; j++) {
        int idx = j * 32 + lane;
        float4 b0 = sB0[idx];
        float4 b1 = sB1[idx];
        float4 b2 = sB2[idx];
        float4 b3 = sB3[idx];
        #pragma unroll
        for (int r = 0; r < 4; r++) {
            float4 o;
            o.x = fmaf(acc[r][0], b0.x, fmaf(acc[r][1], b1.x, fmaf(acc[r][2], b2.x, acc[r][3] * b3.x)));
            o.y = fmaf(acc[r][0], b0.y, fmaf(acc[r][1], b1.y, fmaf(acc[r][2], b2.y, acc[r][3] * b3.y)));
            o.z = fmaf(acc[r][0], b0.z, fmaf(acc[r][1], b1.z, fmaf(acc[r][2], b2.z, acc[r][3] * b3.z)));
            o.w = fmaf(acc[r][0], b0.w, fmaf(acc[r][1], b1.w, fmaf(acc[r][2], b2.w, acc[r][3] * b3.w)));
            stcs4(&orow[r * LORA_NF4 + idx], o);
        }
    }
}

extern "C" void kernel_launch(void* const* d_in, const int* in_sizes, int n_in,
                              void* d_out, int out_size)
{
    const float* x = (const float*)d_in[0];   // [4, 8192, 1024]
    const float* A = (const float*)d_in[1];   // [4, 1024]
    const float* B = (const float*)d_in[2];   // [1024, 4]
    float* out     = (float*)d_out;           // [4, 8192, 1024]

    lora_fused_kernel<<<LORA_GRID, LORA_BLOCK>>>(x, A, B, out);
}